// round 9
// baseline (speedup 1.0000x reference)
#include <cuda_runtime.h>
#include <cuda_fp16.h>
#include <cstdint>

// Problem constants
#define BB   8
#define HH   64
#define WWD  64
#define DD   512
#define NHH  16
#define DKK  32
#define WSS  8
#define SHH  4
#define LL   4
#define MM   (BB*HH*WWD)          // 32768 tokens

// Scratch (device globals)
__device__ __half g_q16 [(size_t)MM * DD];
__device__ __half g_kv16[(size_t)MM * 2 * DD];
__device__ __half g_xn16[(size_t)MM * DD];
__device__ __half g_at16[(size_t)MM * DD];
__device__ __half g_h16 [(size_t)MM * 4 * DD];
__device__ __half g_wq16 [(size_t)LL * DD * DD];
__device__ __half g_wkv16[(size_t)LL * DD * 2 * DD];
__device__ __half g_wo16 [(size_t)LL * DD * DD];
__device__ __half g_w1_16[(size_t)LL * DD * 4 * DD];
__device__ __half g_w2_16[(size_t)LL * 4 * DD * DD];

// ---------------------------------------------------------------------------
// Baseline-PTX helpers
// ---------------------------------------------------------------------------
__device__ __forceinline__ uint32_t smem_to_u32(const void* p) {
    uint32_t a;
    asm("{ .reg .u64 t; cvta.to.shared.u64 t, %1; cvt.u32.u64 %0, t; }" : "=r"(a) : "l"(p));
    return a;
}
__device__ __forceinline__ void cp_async16(uint32_t dst, const void* src) {
    asm volatile("cp.async.cg.shared.global [%0], [%1], 16;" :: "r"(dst), "l"(src));
}
#define CP_COMMIT() asm volatile("cp.async.commit_group;" ::: "memory")
template <int N> __device__ __forceinline__ void cp_wait_group() {
    asm volatile("cp.async.wait_group %0;" :: "n"(N) : "memory");
}
__device__ __forceinline__ void ldsm_x4(uint32_t* r, uint32_t addr) {
    asm volatile("ldmatrix.sync.aligned.m8n8.x4.shared.b16 {%0,%1,%2,%3}, [%4];"
        : "=r"(r[0]), "=r"(r[1]), "=r"(r[2]), "=r"(r[3]) : "r"(addr));
}
__device__ __forceinline__ void ldsm_x4_t(uint32_t* r, uint32_t addr) {
    asm volatile("ldmatrix.sync.aligned.m8n8.x4.trans.shared.b16 {%0,%1,%2,%3}, [%4];"
        : "=r"(r[0]), "=r"(r[1]), "=r"(r[2]), "=r"(r[3]) : "r"(addr));
}
__device__ __forceinline__ void mma_f16(float* c, const uint32_t* a, const uint32_t* b) {
    asm volatile(
        "mma.sync.aligned.m16n8k16.row.col.f32.f16.f16.f32 "
        "{%0,%1,%2,%3}, {%4,%5,%6,%7}, {%8,%9}, {%0,%1,%2,%3};\n"
        : "+f"(c[0]), "+f"(c[1]), "+f"(c[2]), "+f"(c[3])
        : "r"(a[0]), "r"(a[1]), "r"(a[2]), "r"(a[3]), "r"(b[0]), "r"(b[1]));
}

// ---------------------------------------------------------------------------
// fp16 tensor-core GEMM. C = A(MxK) @ B(KxN) + bias
// EPI: 0=none, 1=gelu(tanh), 2=+residual(fp32). OutT: float or __half.
// CTA 128x128, BK=64, 256 threads (8 warps, 64x32 warp tiles), dbuf cp.async.
// 2 CTAs/SM -> 4 warps/SMSP for latency hiding.
// ---------------------------------------------------------------------------
#define HAS_STRIDE 72
#define HBS_STRIDE 136
#define HAS_BUF (128 * HAS_STRIDE)        // halves
#define HBS_BUF (64 * HBS_STRIDE)
#define SMEM_H  ((2 * HAS_BUF + 2 * HBS_BUF) * 2)   // 71680 bytes

__device__ __forceinline__ float gelu_f(float x) {
    float x3 = x * x * x;
    return 0.5f * x * (1.f + tanhf(0.7978845608028654f * (x + 0.044715f * x3)));
}
__device__ __forceinline__ void store2(float* C, size_t off, float v0, float v1) {
    float2 o; o.x = v0; o.y = v1;
    *reinterpret_cast<float2*>(C + off) = o;
}
__device__ __forceinline__ void store2(__half* C, size_t off, float v0, float v1) {
    *reinterpret_cast<__half2*>(C + off) = __floats2half2_rn(v0, v1);
}

template <int EPI, typename OutT>
__global__ void __launch_bounds__(256, 2) hgemm(
    const __half* __restrict__ A, const __half* __restrict__ Bm,
    const float* __restrict__ bias, const float* __restrict__ Rv,
    OutT* __restrict__ C, int M, int N, int K)
{
    extern __shared__ __half smh[];
    uint32_t sb = smem_to_u32(smh);
    const int tid = threadIdx.x;
    const int lane = tid & 31, wid = tid >> 5;
    const int wm = wid & 1, wn = wid >> 1;      // warp tile (wm*64, wn*32)
    const int g = lane >> 2, tg = lane & 3;
    const int row0 = blockIdx.y * 128, col0 = blockIdx.x * 128;

    const int lrow = lane & 15, lcol8 = (lane >> 4) * 8;

    float acc[4][4][4];
#pragma unroll
    for (int i = 0; i < 4; i++)
#pragma unroll
        for (int j = 0; j < 4; j++)
#pragma unroll
            for (int k = 0; k < 4; k++) acc[i][j][k] = 0.f;

    const int NC = K >> 6;    // BK=64 chunks

    // ---- stage chunk 0 into buffer 0 ----
    {
        uint32_t ad = sb, bd = sb + 2 * HAS_BUF * 2;
#pragma unroll
        for (int i = 0; i < 4; i++) {              // A: 128 rows x 8 units(16B)
            int ch = i * 256 + tid;
            int r = ch >> 3, c8 = ch & 7;
            cp_async16(ad + (r * HAS_STRIDE + c8 * 8) * 2,
                       A + (size_t)(row0 + r) * K + c8 * 8);
        }
#pragma unroll
        for (int i = 0; i < 4; i++) {              // B: 64 rows x 16 units
            int ch = i * 256 + tid;
            int r = ch >> 4, c8 = ch & 15;
            cp_async16(bd + (r * HBS_STRIDE + c8 * 8) * 2,
                       Bm + (size_t)r * N + col0 + c8 * 8);
        }
        CP_COMMIT();
    }

    for (int c = 0; c < NC; c++) {
        if (c + 1 < NC) {
            int kt = (c + 1) << 6;
            int nb = (c + 1) & 1;
            uint32_t ad = sb + (nb ? HAS_BUF * 2 : 0);
            uint32_t bd = sb + (2 * HAS_BUF + (nb ? HBS_BUF : 0)) * 2;
#pragma unroll
            for (int i = 0; i < 4; i++) {
                int ch = i * 256 + tid;
                int r = ch >> 3, c8 = ch & 7;
                cp_async16(ad + (r * HAS_STRIDE + c8 * 8) * 2,
                           A + (size_t)(row0 + r) * K + kt + c8 * 8);
            }
#pragma unroll
            for (int i = 0; i < 4; i++) {
                int ch = i * 256 + tid;
                int r = ch >> 4, c8 = ch & 15;
                cp_async16(bd + (r * HBS_STRIDE + c8 * 8) * 2,
                           Bm + (size_t)(kt + r) * N + col0 + c8 * 8);
            }
            CP_COMMIT();
            cp_wait_group<1>();
        } else {
            cp_wait_group<0>();
        }
        __syncthreads();

        uint32_t sbA = sb + ((c & 1) ? HAS_BUF * 2 : 0);
        uint32_t sbB = sb + (2 * HAS_BUF + ((c & 1) ? HBS_BUF : 0)) * 2;

#pragma unroll
        for (int j = 0; j < 4; j++) {             // 4 k-steps of 16
            const int kk = j * 16;
            uint32_t af[4][4], bf[4][2];
#pragma unroll
            for (int mt = 0; mt < 4; mt++) {
                int m = wm * 64 + mt * 16 + lrow;
                ldsm_x4(af[mt], sbA + (m * HAS_STRIDE + kk + lcol8) * 2);
            }
#pragma unroll
            for (int np = 0; np < 2; np++) {
                uint32_t r4[4];
                int n = wn * 32 + np * 16 + lcol8;
                ldsm_x4_t(r4, sbB + ((kk + lrow) * HBS_STRIDE + n) * 2);
                bf[2*np][0] = r4[0]; bf[2*np][1] = r4[1];
                bf[2*np+1][0] = r4[2]; bf[2*np+1][1] = r4[3];
            }
#pragma unroll
            for (int mt = 0; mt < 4; mt++)
#pragma unroll
                for (int nt = 0; nt < 4; nt++)
                    mma_f16(acc[mt][nt], af[mt], bf[nt]);
        }
        __syncthreads();
    }

    // ---- epilogue from registers ----
#pragma unroll
    for (int mt = 0; mt < 4; mt++) {
#pragma unroll
        for (int nt = 0; nt < 4; nt++) {
            int r = row0 + wm * 64 + mt * 16 + g;
            int cc = col0 + wn * 32 + nt * 8 + tg * 2;
            float b0 = bias[cc], b1 = bias[cc + 1];
#pragma unroll
            for (int h = 0; h < 2; h++) {
                int rr = r + h * 8;
                size_t off = (size_t)rr * N + cc;
                float v0 = acc[mt][nt][h * 2 + 0] + b0;
                float v1 = acc[mt][nt][h * 2 + 1] + b1;
                if (EPI == 1) { v0 = gelu_f(v0); v1 = gelu_f(v1); }
                if (EPI == 2) {
                    float2 rv = *reinterpret_cast<const float2*>(Rv + off);
                    v0 += rv.x; v1 += rv.y;
                }
                store2(C, off, v0, v1);
            }
        }
    }
}

// ---------------------------------------------------------------------------
// fp32 -> fp16 conversion (8 elems/thread)
// ---------------------------------------------------------------------------
struct H8 { __half2 h[4]; };
__global__ void f2h_kernel(const float* __restrict__ in, __half* __restrict__ out, int n) {
    int i = (blockIdx.x * blockDim.x + threadIdx.x) * 8;
    if (i >= n) return;
    const float4* p = reinterpret_cast<const float4*>(in + i);
    float4 a = p[0], b = p[1];
    H8 o;
    o.h[0] = __floats2half2_rn(a.x, a.y);
    o.h[1] = __floats2half2_rn(a.z, a.w);
    o.h[2] = __floats2half2_rn(b.x, b.y);
    o.h[3] = __floats2half2_rn(b.z, b.w);
    *reinterpret_cast<H8*>(out + i) = o;
}

// ---------------------------------------------------------------------------
// LayerNorm: one warp per token, fp16 output
// ---------------------------------------------------------------------------
__global__ void ln_kernel(const float* __restrict__ x, const float* __restrict__ g,
                          const float* __restrict__ b, __half* __restrict__ out) {
    int warp = threadIdx.x >> 5, lane = threadIdx.x & 31;
    size_t row = (size_t)blockIdx.x * 8 + warp;
    const float4* xp = reinterpret_cast<const float4*>(x + row * DD);
    float4 v[4];
    float s = 0.f;
#pragma unroll
    for (int i = 0; i < 4; i++) {
        v[i] = xp[lane + i * 32];
        s += v[i].x + v[i].y + v[i].z + v[i].w;
    }
#pragma unroll
    for (int o = 16; o; o >>= 1) s += __shfl_xor_sync(0xFFFFFFFFu, s, o);
    float mean = s * (1.f / DD);
    float vs = 0.f;
#pragma unroll
    for (int i = 0; i < 4; i++) {
        float dx;
        dx = v[i].x - mean; vs += dx * dx;
        dx = v[i].y - mean; vs += dx * dx;
        dx = v[i].z - mean; vs += dx * dx;
        dx = v[i].w - mean; vs += dx * dx;
    }
#pragma unroll
    for (int o = 16; o; o >>= 1) vs += __shfl_xor_sync(0xFFFFFFFFu, vs, o);
    float rs = rsqrtf(vs * (1.f / DD) + 1e-5f);
    const float4* gp = reinterpret_cast<const float4*>(g);
    const float4* bp = reinterpret_cast<const float4*>(b);
#pragma unroll
    for (int i = 0; i < 4; i++) {
        int idx = lane + i * 32;
        float4 gg = gp[idx], bb = bp[idx];
        __half2 h0 = __floats2half2_rn((v[i].x - mean) * rs * gg.x + bb.x,
                                       (v[i].y - mean) * rs * gg.y + bb.y);
        __half2 h1 = __floats2half2_rn((v[i].z - mean) * rs * gg.z + bb.z,
                                       (v[i].w - mean) * rs * gg.w + bb.w);
        __half2 t[2] = { h0, h1 };
        *reinterpret_cast<uint2*>(out + row * DD + idx * 4) = *reinterpret_cast<uint2*>(t);
    }
}

// ---------------------------------------------------------------------------
// Fused shifted-window attention (fp16 q/kv in, fp16 out; fp32 math inside)
// ---------------------------------------------------------------------------
__global__ void __launch_bounds__(64) attn_kernel(
    const __half* __restrict__ q, const __half* __restrict__ kv,
    const float* __restrict__ table, __half* __restrict__ out)
{
    __shared__ float ks [64][DKK];
    __shared__ float vsm[64][DKK];
    __shared__ float ssc[64][65];
    __shared__ float tbl[225];
    __shared__ int   ids[64];

    int win = blockIdx.x;
    int wi = win >> 3, wj = win & 7;
    int head = blockIdx.y, b = blockIdx.z;
    int t = threadIdx.x;

    for (int i = t; i < 225; i += 64) tbl[i] = table[i * NHH + head];

    int r = t >> 3, c = t & 7;
    int hr = wi * 8 + r, wr = wj * 8 + c;
    int hs = (hr + SHH) & (HH - 1);
    int ws2 = (wr + SHH) & (WWD - 1);
    size_t base = ((size_t)(b * HH + hs) * WWD + ws2);

    int rh = (hr < HH - WSS) ? 0 : ((hr < HH - SHH) ? 1 : 2);
    int rw = (wr < WWD - WSS) ? 0 : ((wr < WWD - SHH) ? 1 : 2);
    ids[t] = rh * 3 + rw;

    float qr[DKK];
    {
        const uint4* qp = reinterpret_cast<const uint4*>(q + base * DD + head * DKK);
#pragma unroll
        for (int i = 0; i < 4; i++) {
            uint4 u = qp[i];
            const __half2* hp = reinterpret_cast<const __half2*>(&u);
#pragma unroll
            for (int j2 = 0; j2 < 4; j2++) {
                float2 f = __half22float2(hp[j2]);
                qr[i * 8 + j2 * 2] = f.x; qr[i * 8 + j2 * 2 + 1] = f.y;
            }
        }
        const uint4* kp = reinterpret_cast<const uint4*>(kv + base * 2 * DD + head * DKK);
        const uint4* vp = reinterpret_cast<const uint4*>(kv + base * 2 * DD + DD + head * DKK);
#pragma unroll
        for (int i = 0; i < 4; i++) {
            uint4 u = kp[i];
            const __half2* hp = reinterpret_cast<const __half2*>(&u);
#pragma unroll
            for (int j2 = 0; j2 < 4; j2++) {
                float2 f = __half22float2(hp[j2]);
                ks[t][i * 8 + j2 * 2] = f.x; ks[t][i * 8 + j2 * 2 + 1] = f.y;
            }
            u = vp[i];
#pragma unroll
            for (int j2 = 0; j2 < 4; j2++) {
                float2 f = __half22float2(hp[j2]);
                vsm[t][i * 8 + j2 * 2] = f.x; vsm[t][i * 8 + j2 * 2 + 1] = f.y;
            }
        }
    }
    __syncthreads();

    const float SCALE = 0.17677669529663687f;
    int myid = ids[t];
    float mx = -1e30f;
#pragma unroll 4
    for (int ki = 0; ki < 64; ki++) {
        float d = 0.f;
#pragma unroll
        for (int dd = 0; dd < DKK; dd++) d = fmaf(qr[dd], ks[ki][dd], d);
        int rk = ki >> 3, ck = ki & 7;
        float s = d * SCALE + tbl[(r - rk + 7) * 15 + (c - ck + 7)];
        if (ids[ki] != myid) s = -1e9f;
        ssc[t][ki] = s;
        mx = fmaxf(mx, s);
    }
    float den = 0.f;
#pragma unroll 8
    for (int ki = 0; ki < 64; ki++) {
        float e = __expf(ssc[t][ki] - mx);
        ssc[t][ki] = e;
        den += e;
    }
    float inv = 1.f / den;
    float o[DKK] = {};
#pragma unroll 4
    for (int ki = 0; ki < 64; ki++) {
        float p = ssc[t][ki] * inv;
#pragma unroll
        for (int dd = 0; dd < DKK; dd++) o[dd] = fmaf(p, vsm[ki][dd], o[dd]);
    }
    __half* op = out + base * DD + head * DKK;
#pragma unroll
    for (int i = 0; i < 8; i++) {
        __half2 t0 = __floats2half2_rn(o[i*4],   o[i*4+1]);
        __half2 t1 = __floats2half2_rn(o[i*4+2], o[i*4+3]);
        __half2 tt[2] = { t0, t1 };
        *reinterpret_cast<uint2*>(op + i * 4) = *reinterpret_cast<uint2*>(tt);
    }
}

// ---------------------------------------------------------------------------
extern "C" void kernel_launch(void* const* d_in, const int* in_sizes, int n_in,
                              void* d_out, int out_size) {
    const float* x   = (const float*)d_in[0];
    const float* Wq  = (const float*)d_in[3];
    const float* bq  = (const float*)d_in[4];
    const float* Wkv = (const float*)d_in[5];
    const float* bkv = (const float*)d_in[6];
    const float* Wo  = (const float*)d_in[7];
    const float* bo  = (const float*)d_in[8];
    const float* rt  = (const float*)d_in[9];
    const float* l1g = (const float*)d_in[10];
    const float* l1b = (const float*)d_in[11];
    const float* l2g = (const float*)d_in[12];
    const float* l2b = (const float*)d_in[13];
    const float* W1  = (const float*)d_in[14];
    const float* b1  = (const float*)d_in[15];
    const float* W2  = (const float*)d_in[16];
    const float* b2  = (const float*)d_in[17];
    float* xo = (float*)d_out;

    __half *pq, *pkv, *pxn, *pat, *ph, *wq16, *wkv16, *wo16, *w1_16, *w2_16;
    cudaGetSymbolAddress((void**)&pq,    g_q16);
    cudaGetSymbolAddress((void**)&pkv,   g_kv16);
    cudaGetSymbolAddress((void**)&pxn,   g_xn16);
    cudaGetSymbolAddress((void**)&pat,   g_at16);
    cudaGetSymbolAddress((void**)&ph,    g_h16);
    cudaGetSymbolAddress((void**)&wq16,  g_wq16);
    cudaGetSymbolAddress((void**)&wkv16, g_wkv16);
    cudaGetSymbolAddress((void**)&wo16,  g_wo16);
    cudaGetSymbolAddress((void**)&w1_16, g_w1_16);
    cudaGetSymbolAddress((void**)&w2_16, g_w2_16);

    cudaFuncSetAttribute(hgemm<0, __half>, cudaFuncAttributeMaxDynamicSharedMemorySize, SMEM_H);
    cudaFuncSetAttribute(hgemm<1, __half>, cudaFuncAttributeMaxDynamicSharedMemorySize, SMEM_H);
    cudaFuncSetAttribute(hgemm<2, float>,  cudaFuncAttributeMaxDynamicSharedMemorySize, SMEM_H);

    // convert weights to fp16 (every call: deterministic)
    {
        int n;
        n = LL * DD * DD;
        f2h_kernel<<<(n / 8 + 255) / 256, 256>>>(Wq, wq16, n);
        n = LL * DD * 2 * DD;
        f2h_kernel<<<(n / 8 + 255) / 256, 256>>>(Wkv, wkv16, n);
        n = LL * DD * DD;
        f2h_kernel<<<(n / 8 + 255) / 256, 256>>>(Wo, wo16, n);
        n = LL * DD * 4 * DD;
        f2h_kernel<<<(n / 8 + 255) / 256, 256>>>(W1, w1_16, n);
        n = LL * 4 * DD * DD;
        f2h_kernel<<<(n / 8 + 255) / 256, 256>>>(W2, w2_16, n);
    }

    cudaMemcpyAsync(xo, x, (size_t)MM * DD * sizeof(float),
                    cudaMemcpyDeviceToDevice, 0);

    for (int l = 0; l < LL; l++) {
        ln_kernel<<<MM / 8, 256>>>(xo, l1g + l * DD, l1b + l * DD, pxn);
        hgemm<0, __half><<<dim3(DD / 128, MM / 128), 256, SMEM_H>>>(
            pxn, wq16 + (size_t)l * DD * DD, bq + (size_t)l * DD, nullptr, pq,
            MM, DD, DD);
        hgemm<0, __half><<<dim3(2 * DD / 128, MM / 128), 256, SMEM_H>>>(
            pxn, wkv16 + (size_t)l * DD * 2 * DD, bkv + (size_t)l * 2 * DD, nullptr, pkv,
            MM, 2 * DD, DD);
        attn_kernel<<<dim3(64, NHH, BB), 64>>>(pq, pkv, rt + (size_t)l * 225 * NHH, pat);
        hgemm<2, float><<<dim3(DD / 128, MM / 128), 256, SMEM_H>>>(
            pat, wo16 + (size_t)l * DD * DD, bo + (size_t)l * DD, xo, xo,
            MM, DD, DD);
        ln_kernel<<<MM / 8, 256>>>(xo, l2g + l * DD, l2b + l * DD, pxn);
        hgemm<1, __half><<<dim3(4 * DD / 128, MM / 128), 256, SMEM_H>>>(
            pxn, w1_16 + (size_t)l * DD * 4 * DD, b1 + (size_t)l * 4 * DD, nullptr, ph,
            MM, 4 * DD, DD);
        hgemm<2, float><<<dim3(DD / 128, MM / 128), 256, SMEM_H>>>(
            ph, w2_16 + (size_t)l * 4 * DD * DD, b2 + (size_t)l * DD, xo, xo,
            MM, DD, 4 * DD);
    }
}

// round 10
// speedup vs baseline: 1.5534x; 1.5534x over previous
#include <cuda_runtime.h>
#include <cuda_fp16.h>
#include <cstdint>

// Problem constants
#define BB   8
#define HH   64
#define WWD  64
#define DD   512
#define NHH  16
#define DKK  32
#define WSS  8
#define SHH  4
#define LL   4
#define MM   (BB*HH*WWD)          // 32768 tokens

// Scratch (device globals)
__device__ __half g_q16 [(size_t)MM * DD];
__device__ __half g_kv16[(size_t)MM * 2 * DD];
__device__ __half g_xn16[(size_t)MM * DD];
__device__ __half g_at16[(size_t)MM * DD];
__device__ __half g_h16 [(size_t)MM * 4 * DD];
__device__ __half g_wq16 [(size_t)LL * DD * DD];
__device__ __half g_wkv16[(size_t)LL * DD * 2 * DD];
__device__ __half g_wo16 [(size_t)LL * DD * DD];
__device__ __half g_w1_16[(size_t)LL * DD * 4 * DD];
__device__ __half g_w2_16[(size_t)LL * 4 * DD * DD];

// ---------------------------------------------------------------------------
// Baseline-PTX helpers
// ---------------------------------------------------------------------------
__device__ __forceinline__ uint32_t smem_to_u32(const void* p) {
    uint32_t a;
    asm("{ .reg .u64 t; cvta.to.shared.u64 t, %1; cvt.u32.u64 %0, t; }" : "=r"(a) : "l"(p));
    return a;
}
__device__ __forceinline__ void cp_async16(uint32_t dst, const void* src) {
    asm volatile("cp.async.cg.shared.global [%0], [%1], 16;" :: "r"(dst), "l"(src));
}
#define CP_COMMIT() asm volatile("cp.async.commit_group;" ::: "memory")
template <int N> __device__ __forceinline__ void cp_wait_group() {
    asm volatile("cp.async.wait_group %0;" :: "n"(N) : "memory");
}
__device__ __forceinline__ void ldsm_x4(uint32_t* r, uint32_t addr) {
    asm volatile("ldmatrix.sync.aligned.m8n8.x4.shared.b16 {%0,%1,%2,%3}, [%4];"
        : "=r"(r[0]), "=r"(r[1]), "=r"(r[2]), "=r"(r[3]) : "r"(addr));
}
__device__ __forceinline__ void ldsm_x4_t(uint32_t* r, uint32_t addr) {
    asm volatile("ldmatrix.sync.aligned.m8n8.x4.trans.shared.b16 {%0,%1,%2,%3}, [%4];"
        : "=r"(r[0]), "=r"(r[1]), "=r"(r[2]), "=r"(r[3]) : "r"(addr));
}
__device__ __forceinline__ void mma_f16(float* c, const uint32_t* a, const uint32_t* b) {
    asm volatile(
        "mma.sync.aligned.m16n8k16.row.col.f32.f16.f16.f32 "
        "{%0,%1,%2,%3}, {%4,%5,%6,%7}, {%8,%9}, {%0,%1,%2,%3};\n"
        : "+f"(c[0]), "+f"(c[1]), "+f"(c[2]), "+f"(c[3])
        : "r"(a[0]), "r"(a[1]), "r"(a[2]), "r"(a[3]), "r"(b[0]), "r"(b[1]));
}

// ---------------------------------------------------------------------------
// fp16 tensor-core GEMM. C = A(MxK) @ B(KxN) + bias
// EPI: 0=none, 1=gelu(tanh), 2=+residual(fp32). OutT: float or __half.
// CTA 128x128, BK=64, 128 threads (4 warps, 64x64 warp tiles), dbuf cp.async,
// register-level fragment double-buffering (prefetch k-step j+1 during mma j).
// ---------------------------------------------------------------------------
#define HAS_STRIDE 72
#define HBS_STRIDE 136
#define HAS_BUF (128 * HAS_STRIDE)        // halves
#define HBS_BUF (64 * HBS_STRIDE)
#define SMEM_H  ((2 * HAS_BUF + 2 * HBS_BUF) * 2)   // 71680 bytes

__device__ __forceinline__ float gelu_f(float x) {
    float x3 = x * x * x;
    return 0.5f * x * (1.f + tanhf(0.7978845608028654f * (x + 0.044715f * x3)));
}
__device__ __forceinline__ void store2(float* C, size_t off, float v0, float v1) {
    float2 o; o.x = v0; o.y = v1;
    *reinterpret_cast<float2*>(C + off) = o;
}
__device__ __forceinline__ void store2(__half* C, size_t off, float v0, float v1) {
    *reinterpret_cast<__half2*>(C + off) = __floats2half2_rn(v0, v1);
}

__device__ __forceinline__ void load_frags(
    uint32_t sbA, uint32_t sbB, int kk, int wm, int wn, int lrow, int lcol8,
    uint32_t af[4][4], uint32_t bf[8][2])
{
#pragma unroll
    for (int mt = 0; mt < 4; mt++) {
        int m = wm * 64 + mt * 16 + lrow;
        ldsm_x4(af[mt], sbA + (m * HAS_STRIDE + kk + lcol8) * 2);
    }
#pragma unroll
    for (int np = 0; np < 4; np++) {
        uint32_t r4[4];
        int n = wn * 64 + np * 16 + lcol8;
        ldsm_x4_t(r4, sbB + ((kk + lrow) * HBS_STRIDE + n) * 2);
        bf[2*np][0]   = r4[0]; bf[2*np][1]   = r4[1];
        bf[2*np+1][0] = r4[2]; bf[2*np+1][1] = r4[3];
    }
}

template <int EPI, typename OutT>
__global__ void __launch_bounds__(128, 2) hgemm(
    const __half* __restrict__ A, const __half* __restrict__ Bm,
    const float* __restrict__ bias, const float* __restrict__ Rv,
    OutT* __restrict__ C, int M, int N, int K)
{
    extern __shared__ __half smh[];
    uint32_t sb = smem_to_u32(smh);
    const int tid = threadIdx.x;
    const int lane = tid & 31, wid = tid >> 5;
    const int wm = wid & 1, wn = wid >> 1;      // warp tile origin (wm*64, wn*64)
    const int g = lane >> 2, tg = lane & 3;
    const int row0 = blockIdx.y * 128, col0 = blockIdx.x * 128;
    const int lrow = lane & 15, lcol8 = (lane >> 4) * 8;

    float acc[4][8][4];
#pragma unroll
    for (int i = 0; i < 4; i++)
#pragma unroll
        for (int j = 0; j < 8; j++)
#pragma unroll
            for (int k = 0; k < 4; k++) acc[i][j][k] = 0.f;

    const int NC = K >> 6;    // BK=64 chunks

    // ---- stage chunk 0 into buffer 0 ----
    {
        uint32_t ad = sb, bd = sb + 2 * HAS_BUF * 2;
#pragma unroll
        for (int i = 0; i < 8; i++) {              // A: 128 rows x 8 units(16B)
            int ch = i * 128 + tid;
            int r = ch >> 3, c8 = ch & 7;
            cp_async16(ad + (r * HAS_STRIDE + c8 * 8) * 2,
                       A + (size_t)(row0 + r) * K + c8 * 8);
        }
#pragma unroll
        for (int i = 0; i < 8; i++) {              // B: 64 rows x 16 units
            int ch = i * 128 + tid;
            int r = ch >> 4, c8 = ch & 15;
            cp_async16(bd + (r * HBS_STRIDE + c8 * 8) * 2,
                       Bm + (size_t)r * N + col0 + c8 * 8);
        }
        CP_COMMIT();
    }

    uint32_t af[2][4][4], bf[2][8][2];

    for (int c = 0; c < NC; c++) {
        if (c + 1 < NC) {
            int kt = (c + 1) << 6;
            int nb = (c + 1) & 1;
            uint32_t ad = sb + (nb ? HAS_BUF * 2 : 0);
            uint32_t bd = sb + (2 * HAS_BUF + (nb ? HBS_BUF : 0)) * 2;
#pragma unroll
            for (int i = 0; i < 8; i++) {
                int ch = i * 128 + tid;
                int r = ch >> 3, c8 = ch & 7;
                cp_async16(ad + (r * HAS_STRIDE + c8 * 8) * 2,
                           A + (size_t)(row0 + r) * K + kt + c8 * 8);
            }
#pragma unroll
            for (int i = 0; i < 8; i++) {
                int ch = i * 128 + tid;
                int r = ch >> 4, c8 = ch & 15;
                cp_async16(bd + (r * HBS_STRIDE + c8 * 8) * 2,
                           Bm + (size_t)(kt + r) * N + col0 + c8 * 8);
            }
            CP_COMMIT();
            cp_wait_group<1>();
        } else {
            cp_wait_group<0>();
        }
        __syncthreads();

        uint32_t sbA = sb + ((c & 1) ? HAS_BUF * 2 : 0);
        uint32_t sbB = sb + (2 * HAS_BUF + ((c & 1) ? HBS_BUF : 0)) * 2;

        // prologue: fragments for k-step 0
        load_frags(sbA, sbB, 0, wm, wn, lrow, lcol8, af[0], bf[0]);

#pragma unroll
        for (int j = 0; j < 4; j++) {             // 4 k-steps of 16
            if (j < 3)   // prefetch next k-step while mma of current executes
                load_frags(sbA, sbB, (j + 1) * 16, wm, wn, lrow, lcol8,
                           af[(j + 1) & 1], bf[(j + 1) & 1]);
            const int cur = j & 1;
#pragma unroll
            for (int mt = 0; mt < 4; mt++)
#pragma unroll
                for (int nt = 0; nt < 8; nt++)
                    mma_f16(acc[mt][nt], af[cur][mt], bf[cur][nt]);
        }
        __syncthreads();
    }

    // ---- epilogue from registers ----
#pragma unroll
    for (int mt = 0; mt < 4; mt++) {
#pragma unroll
        for (int nt = 0; nt < 8; nt++) {
            int r = row0 + wm * 64 + mt * 16 + g;
            int cc = col0 + wn * 64 + nt * 8 + tg * 2;
            float b0 = bias[cc], b1 = bias[cc + 1];
#pragma unroll
            for (int h = 0; h < 2; h++) {
                int rr = r + h * 8;
                size_t off = (size_t)rr * N + cc;
                float v0 = acc[mt][nt][h * 2 + 0] + b0;
                float v1 = acc[mt][nt][h * 2 + 1] + b1;
                if (EPI == 1) { v0 = gelu_f(v0); v1 = gelu_f(v1); }
                if (EPI == 2) {
                    float2 rv = *reinterpret_cast<const float2*>(Rv + off);
                    v0 += rv.x; v1 += rv.y;
                }
                store2(C, off, v0, v1);
            }
        }
    }
}

// ---------------------------------------------------------------------------
// fp32 -> fp16 conversion (8 elems/thread)
// ---------------------------------------------------------------------------
struct H8 { __half2 h[4]; };
__global__ void f2h_kernel(const float* __restrict__ in, __half* __restrict__ out, int n) {
    int i = (blockIdx.x * blockDim.x + threadIdx.x) * 8;
    if (i >= n) return;
    const float4* p = reinterpret_cast<const float4*>(in + i);
    float4 a = p[0], b = p[1];
    H8 o;
    o.h[0] = __floats2half2_rn(a.x, a.y);
    o.h[1] = __floats2half2_rn(a.z, a.w);
    o.h[2] = __floats2half2_rn(b.x, b.y);
    o.h[3] = __floats2half2_rn(b.z, b.w);
    *reinterpret_cast<H8*>(out + i) = o;
}

// ---------------------------------------------------------------------------
// LayerNorm: one warp per token, fp16 output
// ---------------------------------------------------------------------------
__global__ void ln_kernel(const float* __restrict__ x, const float* __restrict__ g,
                          const float* __restrict__ b, __half* __restrict__ out) {
    int warp = threadIdx.x >> 5, lane = threadIdx.x & 31;
    size_t row = (size_t)blockIdx.x * 8 + warp;
    const float4* xp = reinterpret_cast<const float4*>(x + row * DD);
    float4 v[4];
    float s = 0.f;
#pragma unroll
    for (int i = 0; i < 4; i++) {
        v[i] = xp[lane + i * 32];
        s += v[i].x + v[i].y + v[i].z + v[i].w;
    }
#pragma unroll
    for (int o = 16; o; o >>= 1) s += __shfl_xor_sync(0xFFFFFFFFu, s, o);
    float mean = s * (1.f / DD);
    float vs = 0.f;
#pragma unroll
    for (int i = 0; i < 4; i++) {
        float dx;
        dx = v[i].x - mean; vs += dx * dx;
        dx = v[i].y - mean; vs += dx * dx;
        dx = v[i].z - mean; vs += dx * dx;
        dx = v[i].w - mean; vs += dx * dx;
    }
#pragma unroll
    for (int o = 16; o; o >>= 1) vs += __shfl_xor_sync(0xFFFFFFFFu, vs, o);
    float rs = rsqrtf(vs * (1.f / DD) + 1e-5f);
    const float4* gp = reinterpret_cast<const float4*>(g);
    const float4* bp = reinterpret_cast<const float4*>(b);
#pragma unroll
    for (int i = 0; i < 4; i++) {
        int idx = lane + i * 32;
        float4 gg = gp[idx], bb = bp[idx];
        __half2 h0 = __floats2half2_rn((v[i].x - mean) * rs * gg.x + bb.x,
                                       (v[i].y - mean) * rs * gg.y + bb.y);
        __half2 h1 = __floats2half2_rn((v[i].z - mean) * rs * gg.z + bb.z,
                                       (v[i].w - mean) * rs * gg.w + bb.w);
        __half2 t[2] = { h0, h1 };
        *reinterpret_cast<uint2*>(out + row * DD + idx * 4) = *reinterpret_cast<uint2*>(t);
    }
}

// ---------------------------------------------------------------------------
// Fused shifted-window attention (fp16 q/kv in, fp16 out; fp32 math inside)
// ---------------------------------------------------------------------------
__global__ void __launch_bounds__(64) attn_kernel(
    const __half* __restrict__ q, const __half* __restrict__ kv,
    const float* __restrict__ table, __half* __restrict__ out)
{
    __shared__ float ks [64][DKK];
    __shared__ float vsm[64][DKK];
    __shared__ float ssc[64][65];
    __shared__ float tbl[225];
    __shared__ int   ids[64];

    int win = blockIdx.x;
    int wi = win >> 3, wj = win & 7;
    int head = blockIdx.y, b = blockIdx.z;
    int t = threadIdx.x;

    for (int i = t; i < 225; i += 64) tbl[i] = table[i * NHH + head];

    int r = t >> 3, c = t & 7;
    int hr = wi * 8 + r, wr = wj * 8 + c;
    int hs = (hr + SHH) & (HH - 1);
    int ws2 = (wr + SHH) & (WWD - 1);
    size_t base = ((size_t)(b * HH + hs) * WWD + ws2);

    int rh = (hr < HH - WSS) ? 0 : ((hr < HH - SHH) ? 1 : 2);
    int rw = (wr < WWD - WSS) ? 0 : ((wr < WWD - SHH) ? 1 : 2);
    ids[t] = rh * 3 + rw;

    float qr[DKK];
    {
        const uint4* qp = reinterpret_cast<const uint4*>(q + base * DD + head * DKK);
#pragma unroll
        for (int i = 0; i < 4; i++) {
            uint4 u = qp[i];
            const __half2* hp = reinterpret_cast<const __half2*>(&u);
#pragma unroll
            for (int j2 = 0; j2 < 4; j2++) {
                float2 f = __half22float2(hp[j2]);
                qr[i * 8 + j2 * 2] = f.x; qr[i * 8 + j2 * 2 + 1] = f.y;
            }
        }
        const uint4* kp = reinterpret_cast<const uint4*>(kv + base * 2 * DD + head * DKK);
        const uint4* vp = reinterpret_cast<const uint4*>(kv + base * 2 * DD + DD + head * DKK);
#pragma unroll
        for (int i = 0; i < 4; i++) {
            uint4 u = kp[i];
            const __half2* hp = reinterpret_cast<const __half2*>(&u);
#pragma unroll
            for (int j2 = 0; j2 < 4; j2++) {
                float2 f = __half22float2(hp[j2]);
                ks[t][i * 8 + j2 * 2] = f.x; ks[t][i * 8 + j2 * 2 + 1] = f.y;
            }
            u = vp[i];
#pragma unroll
            for (int j2 = 0; j2 < 4; j2++) {
                float2 f = __half22float2(hp[j2]);
                vsm[t][i * 8 + j2 * 2] = f.x; vsm[t][i * 8 + j2 * 2 + 1] = f.y;
            }
        }
    }
    __syncthreads();

    const float SCALE = 0.17677669529663687f;
    int myid = ids[t];
    float mx = -1e30f;
#pragma unroll 4
    for (int ki = 0; ki < 64; ki++) {
        float d = 0.f;
#pragma unroll
        for (int dd = 0; dd < DKK; dd++) d = fmaf(qr[dd], ks[ki][dd], d);
        int rk = ki >> 3, ck = ki & 7;
        float s = d * SCALE + tbl[(r - rk + 7) * 15 + (c - ck + 7)];
        if (ids[ki] != myid) s = -1e9f;
        ssc[t][ki] = s;
        mx = fmaxf(mx, s);
    }
    float den = 0.f;
#pragma unroll 8
    for (int ki = 0; ki < 64; ki++) {
        float e = __expf(ssc[t][ki] - mx);
        ssc[t][ki] = e;
        den += e;
    }
    float inv = 1.f / den;
    float o[DKK] = {};
#pragma unroll 4
    for (int ki = 0; ki < 64; ki++) {
        float p = ssc[t][ki] * inv;
#pragma unroll
        for (int dd = 0; dd < DKK; dd++) o[dd] = fmaf(p, vsm[ki][dd], o[dd]);
    }
    __half* op = out + base * DD + head * DKK;
#pragma unroll
    for (int i = 0; i < 8; i++) {
        __half2 t0 = __floats2half2_rn(o[i*4],   o[i*4+1]);
        __half2 t1 = __floats2half2_rn(o[i*4+2], o[i*4+3]);
        __half2 tt[2] = { t0, t1 };
        *reinterpret_cast<uint2*>(op + i * 4) = *reinterpret_cast<uint2*>(tt);
    }
}

// ---------------------------------------------------------------------------
extern "C" void kernel_launch(void* const* d_in, const int* in_sizes, int n_in,
                              void* d_out, int out_size) {
    const float* x   = (const float*)d_in[0];
    const float* Wq  = (const float*)d_in[3];
    const float* bq  = (const float*)d_in[4];
    const float* Wkv = (const float*)d_in[5];
    const float* bkv = (const float*)d_in[6];
    const float* Wo  = (const float*)d_in[7];
    const float* bo  = (const float*)d_in[8];
    const float* rt  = (const float*)d_in[9];
    const float* l1g = (const float*)d_in[10];
    const float* l1b = (const float*)d_in[11];
    const float* l2g = (const float*)d_in[12];
    const float* l2b = (const float*)d_in[13];
    const float* W1  = (const float*)d_in[14];
    const float* b1  = (const float*)d_in[15];
    const float* W2  = (const float*)d_in[16];
    const float* b2  = (const float*)d_in[17];
    float* xo = (float*)d_out;

    __half *pq, *pkv, *pxn, *pat, *ph, *wq16, *wkv16, *wo16, *w1_16, *w2_16;
    cudaGetSymbolAddress((void**)&pq,    g_q16);
    cudaGetSymbolAddress((void**)&pkv,   g_kv16);
    cudaGetSymbolAddress((void**)&pxn,   g_xn16);
    cudaGetSymbolAddress((void**)&pat,   g_at16);
    cudaGetSymbolAddress((void**)&ph,    g_h16);
    cudaGetSymbolAddress((void**)&wq16,  g_wq16);
    cudaGetSymbolAddress((void**)&wkv16, g_wkv16);
    cudaGetSymbolAddress((void**)&wo16,  g_wo16);
    cudaGetSymbolAddress((void**)&w1_16, g_w1_16);
    cudaGetSymbolAddress((void**)&w2_16, g_w2_16);

    cudaFuncSetAttribute(hgemm<0, __half>, cudaFuncAttributeMaxDynamicSharedMemorySize, SMEM_H);
    cudaFuncSetAttribute(hgemm<1, __half>, cudaFuncAttributeMaxDynamicSharedMemorySize, SMEM_H);
    cudaFuncSetAttribute(hgemm<2, float>,  cudaFuncAttributeMaxDynamicSharedMemorySize, SMEM_H);

    // convert weights to fp16 (every call: deterministic)
    {
        int n;
        n = LL * DD * DD;
        f2h_kernel<<<(n / 8 + 255) / 256, 256>>>(Wq, wq16, n);
        n = LL * DD * 2 * DD;
        f2h_kernel<<<(n / 8 + 255) / 256, 256>>>(Wkv, wkv16, n);
        n = LL * DD * DD;
        f2h_kernel<<<(n / 8 + 255) / 256, 256>>>(Wo, wo16, n);
        n = LL * DD * 4 * DD;
        f2h_kernel<<<(n / 8 + 255) / 256, 256>>>(W1, w1_16, n);
        n = LL * 4 * DD * DD;
        f2h_kernel<<<(n / 8 + 255) / 256, 256>>>(W2, w2_16, n);
    }

    cudaMemcpyAsync(xo, x, (size_t)MM * DD * sizeof(float),
                    cudaMemcpyDeviceToDevice, 0);

    for (int l = 0; l < LL; l++) {
        ln_kernel<<<MM / 8, 256>>>(xo, l1g + l * DD, l1b + l * DD, pxn);
        hgemm<0, __half><<<dim3(DD / 128, MM / 128), 128, SMEM_H>>>(
            pxn, wq16 + (size_t)l * DD * DD, bq + (size_t)l * DD, nullptr, pq,
            MM, DD, DD);
        hgemm<0, __half><<<dim3(2 * DD / 128, MM / 128), 128, SMEM_H>>>(
            pxn, wkv16 + (size_t)l * DD * 2 * DD, bkv + (size_t)l * 2 * DD, nullptr, pkv,
            MM, 2 * DD, DD);
        attn_kernel<<<dim3(64, NHH, BB), 64>>>(pq, pkv, rt + (size_t)l * 225 * NHH, pat);
        hgemm<2, float><<<dim3(DD / 128, MM / 128), 128, SMEM_H>>>(
            pat, wo16 + (size_t)l * DD * DD, bo + (size_t)l * DD, xo, xo,
            MM, DD, DD);
        ln_kernel<<<MM / 8, 256>>>(xo, l2g + l * DD, l2b + l * DD, pxn);
        hgemm<1, __half><<<dim3(4 * DD / 128, MM / 128), 128, SMEM_H>>>(
            pxn, w1_16 + (size_t)l * DD * 4 * DD, b1 + (size_t)l * 4 * DD, nullptr, ph,
            MM, 4 * DD, DD);
        hgemm<2, float><<<dim3(DD / 128, MM / 128), 128, SMEM_H>>>(
            ph, w2_16 + (size_t)l * 4 * DD * DD, b2 + (size_t)l * DD, xo, xo,
            MM, DD, 4 * DD);
    }
}